// round 10
// baseline (speedup 1.0000x reference)
#include <cuda_runtime.h>
#include <cstddef>
#include <cstdint>

// Problem shape (fixed by the dataset)
constexpr int B = 8;
constexpr int T = 2048;
constexpr int C = 4096;
constexpr int U = 200;
constexpr int UP = 256;              // padded per-frame stride

// Scratch (no cudaMalloc allowed). g_p pads [U,UP) are NEVER written ->
// stay 0 from static zero-init, which the recursion relies on.
__device__ float g_p[(size_t)B * T * UP];    // 16.8 MB
__device__ float g_partial[B];

// ---------------------------------------------------------------------------
// Kernel 1: per-(b,t) row log-sum-exp + target gather, emitting P = exp(lpt).
// Row t=0 writes only u=0 (u>0 stays 0 from init) so t=0 is a uniform step
// from the A[0]=1 seed. Measured at DRAM roofline (47.5us, 73% DRAM).
// ---------------------------------------------------------------------------
__global__ __launch_bounds__(256) void lse_gather_kernel(
    const float* __restrict__ x, const int* __restrict__ tgt)
{
    const int row = blockIdx.x;          // b*T + t
    const int b   = row >> 11;           // T = 2048
    const int t   = row & (T - 1);
    const int tid = threadIdx.x;

    __shared__ float sh[C];
    __shared__ float red[8];
    __shared__ float s_bcast;

    const float4* r4 = reinterpret_cast<const float4*>(x) + (size_t)row * (C / 4);

    float4 v[4];
    float mx = -3.402823466e38f;
#pragma unroll
    for (int i = 0; i < 4; i++) {
        v[i] = r4[tid + i * 256];
        reinterpret_cast<float4*>(sh)[tid + i * 256] = v[i];
        mx = fmaxf(mx, fmaxf(fmaxf(v[i].x, v[i].y), fmaxf(v[i].z, v[i].w)));
    }

#pragma unroll
    for (int o = 16; o; o >>= 1) mx = fmaxf(mx, __shfl_xor_sync(0xffffffffu, mx, o));
    if ((tid & 31) == 0) red[tid >> 5] = mx;
    __syncthreads();
    if (tid == 0) {
        float m = red[0];
#pragma unroll
        for (int w = 1; w < 8; w++) m = fmaxf(m, red[w]);
        s_bcast = m;
    }
    __syncthreads();
    mx = s_bcast;

    float s = 0.f;
#pragma unroll
    for (int i = 0; i < 4; i++) {
        s += __expf(v[i].x - mx) + __expf(v[i].y - mx)
           + __expf(v[i].z - mx) + __expf(v[i].w - mx);
    }
#pragma unroll
    for (int o = 16; o; o >>= 1) s += __shfl_xor_sync(0xffffffffu, s, o);
    __syncthreads();
    if ((tid & 31) == 0) red[tid >> 5] = s;
    __syncthreads();
    if (tid == 0) {
        float tt = 0.f;
#pragma unroll
        for (int w = 0; w < 8; w++) tt += red[w];
        s_bcast = mx + __logf(tt);
    }
    __syncthreads();
    const float lse = s_bcast;

    // P = exp(lpt); pads and (t==0,u>0) remain zero (never written)
    if (tid < U && (t > 0 || tid == 0)) {
        const int c = tgt[b * U + tid] & (C - 1);
        g_p[(size_t)row * UP + tid] = __expf(sh[c] - lse);
    }
}

// ---------------------------------------------------------------------------
// Kernel 2 v5b: two compute warps + one copy warp per batch.
//   warp 0: u in [0,128), 4 cells/lane, processes chunk ch at iteration ch;
//           writes per-step boundary (A[127] mantissa + exponent) into the
//           dead pad columns (252/253; carry at 254/255) of its chunk slot.
//   warp 1: u in [128,256), runs ONE CHUNK BEHIND, converting the boundary
//           into its own scale with exact 2^k bit arithmetic. Pad junk only
//           ever reaches lanes 30-31; the output lane is 17.
//   warp 2: triple-slot cp.async staging (slot s re-staged only after warp 1
//           released it at the preceding sync-B).
// No cross-block traffic (finalize is a separate kernel).
// ---------------------------------------------------------------------------
constexpr int TS    = 16;            // time steps per staged chunk
constexpr int NCH   = T / TS;        // 128 chunks
constexpr int CHUNK = TS * UP;       // 4096 floats = 16 KB

__device__ __forceinline__ void cp_chunk(float* dst_sh, const float* src_g, int lane)
{
    uint32_t d = (uint32_t)__cvta_generic_to_shared(dst_sh) + lane * 16;
    const char* s = reinterpret_cast<const char*>(src_g) + lane * 16;
#pragma unroll
    for (int i = 0; i < 32; i++) {
        asm volatile("cp.async.ca.shared.global [%0], [%1], 16;\n"
                     :: "r"(d + i * 512), "l"(s + i * 512));
    }
    asm volatile("cp.async.commit_group;\n");
}

__device__ __forceinline__ float exp2i(int d)    // exact 2^d, d in [-126,127]
{
    return __uint_as_float((uint32_t)(127 + d) << 23);
}

__global__ __launch_bounds__(96) void alpha_kernel()
{
    const int b    = blockIdx.x;
    const int tid  = threadIdx.x;
    const int lane = tid & 31;
    const int wid  = tid >> 5;

    __shared__ alignas(16) float buf[3][CHUNK];   // exactly 48 KB

    const float* gp = g_p + (size_t)b * T * UP;

    // copy-warp prologue: stage chunks 0 and 1
    if (wid == 2) {
        cp_chunk(buf[0], gp, lane);
        cp_chunk(buf[1], gp + CHUNK, lane);
    }

    // compute state (both compute warps)
    float A[4] = {0.f, 0.f, 0.f, 0.f};
    if (wid == 0 && lane == 0) A[0] = 1.f;   // seed (t=0 uniform step)
    int   E = 0;
    float f = 1.f;
    float carryV = 0.f;  int carryE = 0;     // warp0: boundary of step t-1
    int   lastBndE = 0;                      // warp1: last boundary exponent seen

    for (int ch = 0; ch <= NCH; ch++) {
        if (wid == 2 && ch < NCH)
            asm volatile("cp.async.wait_group 1;\n" ::: "memory");
        __syncthreads();                     // A: chunk ch ready (and ch-1 kept)

        if (wid == 0 && ch < NCH) {
            float* bp = buf[ch % 3];
            if (lane == 31) {                // carry: boundary of t = 16ch - 1
                bp[254] = carryV;
                bp[255] = __int_as_float(carryE);
            }
#pragma unroll
            for (int tr = 0; tr < TS; tr++) {
                const float4 pv = reinterpret_cast<const float4*>(bp + tr * UP)[lane];
                const float p[4] = {pv.x, pv.y, pv.z, pv.w};

                const float left = __shfl_up_sync(0xffffffffu, A[3], 1);
                float prev = (lane == 0) ? 0.f : left * f;
#pragma unroll
                for (int j = 0; j < 4; j++) {
                    const float nv = (A[j] + prev) * p[j];
                    prev = A[j];
                    A[j] = nv;
                }
                if ((tr & 3) == 3) {
                    float m = fmaxf(fmaxf(A[0], A[1]), fmaxf(A[2], A[3]));
                    const int e  = (int)(__float_as_uint(m) >> 23) - 127;
                    int cn = E + e;
                    const int cl = __shfl_up_sync(0xffffffffu, cn, 1);
                    if (m == 0.f && lane > 0) cn = cl;
                    const float inv = __uint_as_float((uint32_t)(127 - e) << 23);
#pragma unroll
                    for (int j = 0; j < 4; j++) A[j] *= inv;
                    E = cn;
                    int d = cl - E;
                    d = (d > 120) ? 120 : d;
                    f = (d < -126) ? 0.f : exp2i(d);
                    if (lane == 0) f = 1.f;
                }
                if (lane == 31) {            // boundary of step t = 16ch + tr
                    bp[tr * UP + 252] = A[3];
                    bp[tr * UP + 253] = __int_as_float(E);
                }
            }
            carryV = A[3];
            carryE = E;
        }

        if (wid == 1 && ch >= 1) {
            const float* bp = buf[(ch - 1) % 3];
#pragma unroll
            for (int tr = 0; tr < TS; tr++) {
                const float4 pv = reinterpret_cast<const float4*>(bp + tr * UP)[32 + lane];
                const float p[4] = {pv.x, pv.y, pv.z, pv.w};

                // boundary alpha[t-1, 127]: mantissa + exponent, exact rescale
                const int off = (tr == 0) ? 254 : (tr - 1) * UP + 252;
                const float bV = bp[off];
                const int   bE = __float_as_int(bp[off + 1]);
                lastBndE = bE;
                int dd = bE - E;
                dd = (dd > 120) ? 120 : dd;
                const float f0 = (dd < -126) ? 0.f : exp2i(dd);
                const float prev0 = bV * f0;

                const float left = __shfl_up_sync(0xffffffffu, A[3], 1);
                float prev = (lane == 0) ? prev0 : left * f;
#pragma unroll
                for (int j = 0; j < 4; j++) {
                    const float nv = (A[j] + prev) * p[j];
                    prev = A[j];
                    A[j] = nv;
                }
                if ((tr & 3) == 3) {
                    float m = fmaxf(fmaxf(A[0], A[1]), fmaxf(A[2], A[3]));
                    const int e  = (int)(__float_as_uint(m) >> 23) - 127;
                    int cn = E + e;
                    const int cl = __shfl_up_sync(0xffffffffu, cn, 1);
                    if (m == 0.f) cn = (lane == 0) ? lastBndE : cl;
                    const float inv = __uint_as_float((uint32_t)(127 - e) << 23);
#pragma unroll
                    for (int j = 0; j < 4; j++) A[j] *= inv;
                    E = cn;
                    int d = cl - E;
                    d = (d > 120) ? 120 : d;
                    f = (d < -126) ? 0.f : exp2i(d);
                }
            }
            if (ch == NCH && lane == 17) {   // u = 128 + 17*4 + 3 = 199
                g_partial[b] =
                    (float)(log((double)A[3]) + (double)E * 0.6931471805599453);
            }
        }

        __syncthreads();                     // B: slots released
        if (wid == 2 && ch + 2 < NCH)
            cp_chunk(buf[(ch + 2) % 3], gp + (size_t)(ch + 2) * CHUNK, lane);
    }
}

// ---------------------------------------------------------------------------
// Kernel 3: deterministic final reduction (fixed order).
// ---------------------------------------------------------------------------
__global__ void finalize_kernel(float* __restrict__ out)
{
    float s = 0.f;
#pragma unroll
    for (int b = 0; b < B; b++) s += g_partial[b];
    out[0] = -s / (float)B;
}

extern "C" void kernel_launch(void* const* d_in, const int* in_sizes, int n_in,
                              void* d_out, int out_size)
{
    const float* x   = (const float*)d_in[0];   // [B, T, C] fp32
    const int*   tgt = (const int*)d_in[1];     // [B, U] int32
    float*       out = (float*)d_out;           // scalar fp32

    lse_gather_kernel<<<B * T, 256>>>(x, tgt);
    alpha_kernel<<<B, 96>>>();
    finalize_kernel<<<1, 1>>>(out);
}